// round 2
// baseline (speedup 1.0000x reference)
#include <cuda_runtime.h>
#include <math.h>

// ---------------------------------------------------------------------------
// Spatial_RNN: UNet-ish CNN -> tanh feature map -> 8-direction linear RNN ->
// sigmoid output conv.  B=8, img 15x256x256.
// R2: conv inner loops use packed fma.rn.f32x2 (2 pixels per instruction).
// ---------------------------------------------------------------------------

#define ACT_NONE 0
#define ACT_RELU 1
#define ACT_TANH 2
#define ACT_SIG  3

// ---- scratch buffer partition (floats) ----
constexpr size_t N_X1   = 8ull*16*256*256;
constexpr size_t N_P1   = 8ull*16*128*128;
constexpr size_t N_X2   = 8ull*32*128*128;
constexpr size_t N_P2   = 8ull*32*64*64;
constexpr size_t N_X3   = 8ull*32*64*64;
constexpr size_t N_P3   = 8ull*32*32*32;
constexpr size_t N_X4   = 8ull*32*32*32;
constexpr size_t N_P4   = 8ull*32*16*16;
constexpr size_t N_X5   = 8ull*64*16*16;
constexpr size_t N_U5   = 8ull*64*32*32;
constexpr size_t N_X6   = 8ull*32*32*32;
constexpr size_t N_U6   = 8ull*32*64*64;
constexpr size_t N_X7   = 8ull*32*64*64;
constexpr size_t N_U7   = 8ull*32*128*128;
constexpr size_t N_X8   = 8ull*32*128*128;
constexpr size_t N_U8   = 8ull*32*256*256;
constexpr size_t N_FM   = 8ull*64*256*256;
constexpr size_t N_XIN  = 8ull*16*256*256;
constexpr size_t N_RMAX = 8ull*16*256*256;

constexpr size_t O_X1   = 0;
constexpr size_t O_P1   = O_X1   + N_X1;
constexpr size_t O_X2   = O_P1   + N_P1;
constexpr size_t O_P2   = O_X2   + N_X2;
constexpr size_t O_X3   = O_P2   + N_P2;
constexpr size_t O_P3   = O_X3   + N_X3;
constexpr size_t O_X4   = O_P3   + N_P3;
constexpr size_t O_P4   = O_X4   + N_X4;
constexpr size_t O_X5   = O_P4   + N_P4;
constexpr size_t O_U5   = O_X5   + N_X5;
constexpr size_t O_X6   = O_U5   + N_U5;
constexpr size_t O_U6   = O_X6   + N_X6;
constexpr size_t O_X7   = O_U6   + N_U6;
constexpr size_t O_U7   = O_X7   + N_X7;
constexpr size_t O_X8   = O_U7   + N_U7;
constexpr size_t O_U8   = O_X8   + N_X8;
constexpr size_t O_FM   = O_U8   + N_U8;
constexpr size_t O_XIN  = O_FM   + N_FM;
constexpr size_t O_RMAX = O_XIN  + N_XIN;
constexpr size_t N_TOTAL = O_RMAX + N_RMAX;   // ~384 MB

__device__ float g_buf[N_TOTAL];

// ---- packed f32x2 helpers (Blackwell sm_10x) ----
__device__ __forceinline__ unsigned long long pk2(float lo, float hi) {
    unsigned long long r;
    asm("mov.b64 %0, {%1, %2};" : "=l"(r) : "f"(lo), "f"(hi));
    return r;
}
__device__ __forceinline__ void upk2(float& lo, float& hi, unsigned long long v) {
    asm("mov.b64 {%0, %1}, %2;" : "=f"(lo), "=f"(hi) : "l"(v));
}
__device__ __forceinline__ void fma2(unsigned long long& d,
                                     unsigned long long a,
                                     unsigned long long b) {
    asm("fma.rn.f32x2 %0, %1, %2, %0;" : "+l"(d) : "l"(a), "l"(b));
}

// ---------------------------------------------------------------------------
// Direct conv: 16x16 spatial tile per block, 128 threads, 2 pixels/thread
// (rows ty and ty+8) packed into f32x2.  Weights staged in smem duplicated
// (w,w) so one broadcast LDS.64 feeds one fma.rn.f32x2.
// Input may be a channel-concat of two tensors (A then B).  co0/Ctot split
// Cout across launches.  All H,W are multiples of 16.
// ---------------------------------------------------------------------------
template<int K, int COUT, int ACT>
__global__ void __launch_bounds__(128) conv_kernel(
    const float* __restrict__ inA, int CA,
    const float* __restrict__ inB, int CB,
    const float* __restrict__ wgt, const float* __restrict__ bias,
    float* __restrict__ out, int H, int W, int co0, int Ctot)
{
    constexpr int KK  = K * K;
    constexpr int PAD = K / 2;
    constexpr int S   = 16 + K - 1;
    __shared__ float s_in[S * S];
    __shared__ __align__(8) float s_w2[COUT * KK * 2];

    const int tx = threadIdx.x & 15;
    const int ty = threadIdx.x >> 4;          // 0..7
    const int x0 = blockIdx.x * 16, y0 = blockIdx.y * 16;
    const int b  = blockIdx.z;
    const int Cin = CA + CB;
    const size_t HW = (size_t)H * W;

    unsigned long long acc[COUT];
#pragma unroll
    for (int i = 0; i < COUT; i++) acc[i] = 0ull;

    for (int cin = 0; cin < Cin; cin++) {
        const float* src = (cin < CA)
            ? inA + ((size_t)b * CA + cin) * HW
            : inB + ((size_t)b * CB + (cin - CA)) * HW;

        __syncthreads();   // protect previous iteration's smem reads
        for (int i = threadIdx.x; i < S * S; i += 128) {
            int iy = i / S, ix = i - iy * S;
            int gy = y0 + iy - PAD, gx = x0 + ix - PAD;
            float v = 0.f;
            if ((unsigned)gy < (unsigned)H && (unsigned)gx < (unsigned)W)
                v = src[(size_t)gy * W + gx];
            s_in[i] = v;
        }
        for (int i = threadIdx.x; i < COUT * KK; i += 128) {
            int co = i / KK, k = i - co * KK;
            float w = wgt[((size_t)(co0 + co) * Cin + cin) * KK + k];
            s_w2[2 * i]     = w;
            s_w2[2 * i + 1] = w;
        }
        __syncthreads();

        unsigned long long v01[KK];
#pragma unroll
        for (int ky = 0; ky < K; ky++)
#pragma unroll
            for (int kx = 0; kx < K; kx++)
                v01[ky * K + kx] = pk2(s_in[(ty     + ky) * S + tx + kx],
                                       s_in[(ty + 8 + ky) * S + tx + kx]);

#pragma unroll
        for (int co = 0; co < COUT; co++) {
#pragma unroll
            for (int k = 0; k < KK; k++) {
                unsigned long long wp =
                    *reinterpret_cast<const unsigned long long*>(
                        &s_w2[2 * (co * KK + k)]);
                fma2(acc[co], v01[k], wp);
            }
        }
    }

    const int x = x0 + tx;
    const int y = y0 + ty;
    size_t base = ((size_t)b * Ctot + co0) * HW + (size_t)y * W + x;
#pragma unroll
    for (int co = 0; co < COUT; co++) {
        float s0, s1;
        upk2(s0, s1, acc[co]);
        float bb = bias[co0 + co];
        s0 += bb; s1 += bb;
        if (ACT == ACT_RELU) { s0 = fmaxf(s0, 0.f); s1 = fmaxf(s1, 0.f); }
        else if (ACT == ACT_TANH) { s0 = tanhf(s0); s1 = tanhf(s1); }
        else if (ACT == ACT_SIG)  { s0 = 1.f / (1.f + expf(-s0));
                                    s1 = 1.f / (1.f + expf(-s1)); }
        out[base + (size_t)co * HW]                 = s0;
        out[base + (size_t)co * HW + (size_t)8 * W] = s1;
    }
}

// ---------------------------------------------------------------------------
// 2x2 maxpool (stride 2)
// ---------------------------------------------------------------------------
__global__ void maxpool_kernel(const float* __restrict__ in,
                               float* __restrict__ out,
                               int n, int Ho, int Wo)
{
    int idx = blockIdx.x * 256 + threadIdx.x;
    if (idx >= n) return;
    int x = idx % Wo;
    int t = idx / Wo;
    int y = t % Ho;
    int bc = t / Ho;
    int Wi = Wo * 2;
    const float* p = in + ((size_t)bc * (Ho * 2) + 2 * y) * Wi + 2 * x;
    float a = fmaxf(p[0], p[1]);
    float c = fmaxf(p[Wi], p[Wi + 1]);
    out[idx] = fmaxf(a, c);
}

// ---------------------------------------------------------------------------
// 2x bilinear upsample, half-pixel centers, edge clamp
// ---------------------------------------------------------------------------
__global__ void upsample_kernel(const float* __restrict__ in,
                                float* __restrict__ out,
                                int n, int Hi, int Wi)
{
    int idx = blockIdx.x * 256 + threadIdx.x;
    if (idx >= n) return;
    int Wo = Wi * 2, Ho = Hi * 2;
    int x = idx % Wo;
    int t = idx / Wo;
    int y = t % Ho;
    int bc = t / Ho;
    int xi = x >> 1, yi = y >> 1;
    int xa, xb; float wxa;
    if (x & 1) { xa = xi; xb = min(xi + 1, Wi - 1); wxa = 0.75f; }
    else       { xa = max(xi - 1, 0); xb = xi;      wxa = 0.25f; }
    int ya, yb; float wya;
    if (y & 1) { ya = yi; yb = min(yi + 1, Hi - 1); wya = 0.75f; }
    else       { ya = max(yi - 1, 0); yb = yi;      wya = 0.25f; }
    const float* p = in + (size_t)bc * Hi * Wi;
    float r0 = wxa * p[ya * Wi + xa] + (1.f - wxa) * p[ya * Wi + xb];
    float r1 = wxa * p[yb * Wi + xa] + (1.f - wxa) * p[yb * Wi + xb];
    out[idx] = wya * r0 + (1.f - wya) * r1;
}

// ---------------------------------------------------------------------------
// LRNN.  h_k = (1-p_k)*x_k + p_k*h_{k-1}.  Flipped directions keep outputs
// in SCAN order, so one ascending pass computes all 4 directions of one
// orientation writing at index k (backward scans read index L-1-k).
// Horizontal: P channels {c, 32+c};  Vertical: {16+c, 48+c}.
// ---------------------------------------------------------------------------
__global__ void lrnn_h_kernel(const float* __restrict__ xin,
                              const float* __restrict__ fm,
                              float* __restrict__ out)
{
    int r = blockIdx.x * 256 + threadIdx.x;      // over 8*16*256 rows
    if (r >= 8 * 16 * 256) return;
    int y = r & 255;
    int c = (r >> 8) & 15;
    int b = r >> 12;
    const float* X  = xin + (((size_t)b * 16 + c) << 16) + (size_t)y * 256;
    const float* P0 = fm  + (((size_t)b * 64 + c)      << 16) + (size_t)y * 256;
    const float* P2 = fm  + (((size_t)b * 64 + 32 + c) << 16) + (size_t)y * 256;
    float* O        = out + (((size_t)b * 16 + c) << 16) + (size_t)y * 256;
    float h0 = 0.f, h1 = 0.f, h2 = 0.f, h3 = 0.f;
    for (int k = 0; k < 256; k++) {
        int j = 255 - k;
        float xf = X[k], xb = X[j];
        float p0 = P0[k], p1 = P2[k], p2 = P0[j], p3 = P2[j];
        h0 = xf + p0 * (h0 - xf);
        h1 = xf + p1 * (h1 - xf);
        h2 = xb + p2 * (h2 - xb);
        h3 = xb + p3 * (h3 - xb);
        O[k] = fmaxf(fmaxf(h0, h1), fmaxf(h2, h3));
    }
}

__global__ void lrnn_v_kernel(const float* __restrict__ xin,
                              const float* __restrict__ fm,
                              float* __restrict__ out)
{
    int r = blockIdx.x * 256 + threadIdx.x;      // over 8*16*256 columns
    if (r >= 8 * 16 * 256) return;
    int x = r & 255;
    int c = (r >> 8) & 15;
    int b = r >> 12;
    const float* X  = xin + (((size_t)b * 16 + c) << 16) + x;
    const float* P1 = fm  + (((size_t)b * 64 + 16 + c) << 16) + x;
    const float* P3 = fm  + (((size_t)b * 64 + 48 + c) << 16) + x;
    float* O        = out + (((size_t)b * 16 + c) << 16) + x;
    float h0 = 0.f, h1 = 0.f, h2 = 0.f, h3 = 0.f;
    for (int k = 0; k < 256; k++) {
        int ko = k << 8;
        int jo = (255 - k) << 8;
        float xf = X[ko], xb = X[jo];
        float p0 = P1[ko], p1 = P3[ko], p2 = P1[jo], p3 = P3[jo];
        h0 = xf + p0 * (h0 - xf);
        h1 = xf + p1 * (h1 - xf);
        h2 = xb + p2 * (h2 - xb);
        h3 = xb + p3 * (h3 - xb);
        float m = fmaxf(fmaxf(h0, h1), fmaxf(h2, h3));
        O[ko] = fmaxf(O[ko], m);
    }
}

// ---------------------------------------------------------------------------
// launch
// ---------------------------------------------------------------------------
extern "C" void kernel_launch(void* const* d_in, const int* in_sizes, int n_in,
                              void* d_out, int out_size)
{
    const float* img = (const float*)d_in[0];
    const float* w1 = (const float*)d_in[1],  *b1 = (const float*)d_in[2];
    const float* w2 = (const float*)d_in[3],  *b2 = (const float*)d_in[4];
    const float* w3 = (const float*)d_in[5],  *b3 = (const float*)d_in[6];
    const float* w4 = (const float*)d_in[7],  *b4 = (const float*)d_in[8];
    const float* w5 = (const float*)d_in[9],  *b5 = (const float*)d_in[10];
    const float* w6 = (const float*)d_in[11], *b6 = (const float*)d_in[12];
    const float* w7 = (const float*)d_in[13], *b7 = (const float*)d_in[14];
    const float* w8 = (const float*)d_in[15], *b8 = (const float*)d_in[16];
    const float* w9 = (const float*)d_in[17], *b9 = (const float*)d_in[18];
    const float* wi = (const float*)d_in[19], *bi = (const float*)d_in[20];
    const float* wo = (const float*)d_in[21], *bo = (const float*)d_in[22];
    float* outp = (float*)d_out;

    float* buf = nullptr;
    cudaGetSymbolAddress((void**)&buf, g_buf);
    float* X1 = buf + O_X1;  float* P1 = buf + O_P1;
    float* X2 = buf + O_X2;  float* P2 = buf + O_P2;
    float* X3 = buf + O_X3;  float* P3 = buf + O_P3;
    float* X4 = buf + O_X4;  float* P4 = buf + O_P4;
    float* X5 = buf + O_X5;  float* U5 = buf + O_U5;
    float* X6 = buf + O_X6;  float* U6 = buf + O_U6;
    float* X7 = buf + O_X7;  float* U7 = buf + O_U7;
    float* X8 = buf + O_X8;  float* U8 = buf + O_U8;
    float* FM = buf + O_FM;  float* XIN = buf + O_XIN;
    float* RMAX = buf + O_RMAX;

    auto grid = [](int W, int H) { return dim3(W / 16, H / 16, 8); };
    auto eg = [](size_t n) { return dim3((unsigned)((n + 255) / 256)); };

    // encoder
    conv_kernel<5,16,ACT_RELU><<<grid(256,256),128>>>(img,15, nullptr,0, w1,b1, X1, 256,256, 0,16);
    maxpool_kernel<<<eg(N_P1),256>>>(X1, P1, (int)N_P1, 128,128);
    conv_kernel<3,32,ACT_RELU><<<grid(128,128),128>>>(P1,16, nullptr,0, w2,b2, X2, 128,128, 0,32);
    maxpool_kernel<<<eg(N_P2),256>>>(X2, P2, (int)N_P2, 64,64);
    conv_kernel<3,32,ACT_RELU><<<grid(64,64),128>>>(P2,32, nullptr,0, w3,b3, X3, 64,64, 0,32);
    maxpool_kernel<<<eg(N_P3),256>>>(X3, P3, (int)N_P3, 32,32);
    conv_kernel<3,32,ACT_RELU><<<grid(32,32),128>>>(P3,32, nullptr,0, w4,b4, X4, 32,32, 0,32);
    maxpool_kernel<<<eg(N_P4),256>>>(X4, P4, (int)N_P4, 16,16);
    conv_kernel<3,32,ACT_RELU><<<grid(16,16),128>>>(P4,32, nullptr,0, w5,b5, X5, 16,16, 0,64);
    conv_kernel<3,32,ACT_RELU><<<grid(16,16),128>>>(P4,32, nullptr,0, w5,b5, X5, 16,16, 32,64);

    // decoder
    upsample_kernel<<<eg(N_U5),256>>>(X5, U5, (int)N_U5, 16,16);
    conv_kernel<3,32,ACT_RELU><<<grid(32,32),128>>>(U5,64, X4,32, w6,b6, X6, 32,32, 0,32);
    upsample_kernel<<<eg(N_U6),256>>>(X6, U6, (int)N_U6, 32,32);
    conv_kernel<3,32,ACT_RELU><<<grid(64,64),128>>>(U6,32, X3,32, w7,b7, X7, 64,64, 0,32);
    upsample_kernel<<<eg(N_U7),256>>>(X7, U7, (int)N_U7, 64,64);
    conv_kernel<3,32,ACT_RELU><<<grid(128,128),128>>>(U7,32, X2,32, w8,b8, X8, 128,128, 0,32);
    upsample_kernel<<<eg(N_U8),256>>>(X8, U8, (int)N_U8, 128,128);
    conv_kernel<3,32,ACT_TANH><<<grid(256,256),128>>>(U8,32, X1,16, w9,b9, FM, 256,256, 0,64);
    conv_kernel<3,32,ACT_TANH><<<grid(256,256),128>>>(U8,32, X1,16, w9,b9, FM, 256,256, 32,64);

    // input projection
    conv_kernel<3,16,ACT_NONE><<<grid(256,256),128>>>(img,15, nullptr,0, wi,bi, XIN, 256,256, 0,16);

    // spatial RNN: horizontal pass writes RMAX, vertical pass max-combines
    lrnn_h_kernel<<<128,256>>>(XIN, FM, RMAX);
    lrnn_v_kernel<<<128,256>>>(XIN, FM, RMAX);

    // output conv + sigmoid
    conv_kernel<3,3,ACT_SIG><<<grid(256,256),128>>>(RMAX,16, nullptr,0, wo,bo, outp, 256,256, 0,3);
}

// round 3
// speedup vs baseline: 1.4981x; 1.4981x over previous
#include <cuda_runtime.h>
#include <math.h>

// ---------------------------------------------------------------------------
// Spatial_RNN: UNet-ish CNN -> tanh feature map -> 8-direction linear RNN ->
// sigmoid output conv.  B=8, img 15x256x256.
// R3: scalar FFMA conv, 4 rows/thread, transposed smem weights with float4
// broadcast loads, Cout chunks folded into gridDim.z, small tiles for deep
// (low-parallelism) layers.
// ---------------------------------------------------------------------------

#define ACT_NONE 0
#define ACT_RELU 1
#define ACT_TANH 2
#define ACT_SIG  3

// ---- scratch buffer partition (floats) ----
constexpr size_t N_X1   = 8ull*16*256*256;
constexpr size_t N_P1   = 8ull*16*128*128;
constexpr size_t N_X2   = 8ull*32*128*128;
constexpr size_t N_P2   = 8ull*32*64*64;
constexpr size_t N_X3   = 8ull*32*64*64;
constexpr size_t N_P3   = 8ull*32*32*32;
constexpr size_t N_X4   = 8ull*32*32*32;
constexpr size_t N_P4   = 8ull*32*16*16;
constexpr size_t N_X5   = 8ull*64*16*16;
constexpr size_t N_U5   = 8ull*64*32*32;
constexpr size_t N_X6   = 8ull*32*32*32;
constexpr size_t N_U6   = 8ull*32*64*64;
constexpr size_t N_X7   = 8ull*32*64*64;
constexpr size_t N_U7   = 8ull*32*128*128;
constexpr size_t N_X8   = 8ull*32*128*128;
constexpr size_t N_U8   = 8ull*32*256*256;
constexpr size_t N_FM   = 8ull*64*256*256;
constexpr size_t N_XIN  = 8ull*16*256*256;
constexpr size_t N_RMAX = 8ull*16*256*256;

constexpr size_t O_X1   = 0;
constexpr size_t O_P1   = O_X1   + N_X1;
constexpr size_t O_X2   = O_P1   + N_P1;
constexpr size_t O_P2   = O_X2   + N_X2;
constexpr size_t O_X3   = O_P2   + N_P2;
constexpr size_t O_P3   = O_X3   + N_X3;
constexpr size_t O_X4   = O_P3   + N_P3;
constexpr size_t O_P4   = O_X4   + N_X4;
constexpr size_t O_X5   = O_P4   + N_P4;
constexpr size_t O_U5   = O_X5   + N_X5;
constexpr size_t O_X6   = O_U5   + N_U5;
constexpr size_t O_U6   = O_X6   + N_X6;
constexpr size_t O_X7   = O_U6   + N_U6;
constexpr size_t O_U7   = O_X7   + N_X7;
constexpr size_t O_X8   = O_U7   + N_U7;
constexpr size_t O_U8   = O_X8   + N_X8;
constexpr size_t O_FM   = O_U8   + N_U8;
constexpr size_t O_XIN  = O_FM   + N_FM;
constexpr size_t O_RMAX = O_XIN  + N_XIN;
constexpr size_t N_TOTAL = O_RMAX + N_RMAX;   // ~384 MB

__device__ float g_buf[N_TOTAL];

// ---------------------------------------------------------------------------
// Direct conv.
//   tile: 16 wide x (8*RPT) tall, 128 threads, RPT rows per thread.
//   COC output channels per block (chunk); chunk folded into blockIdx.z:
//     z = b*nChunk + chunk.
//   weights staged transposed: s_w[k*COC + co] -> float4 broadcast loads
//     when COC % 4 == 0.
//   SW padding chosen for conflict-free row-pair LDS (18 for K=3, 22 for K=5).
// ---------------------------------------------------------------------------
template<int K, int COC, int ACT, int RPT>
__global__ void __launch_bounds__(128) conv_kernel(
    const float* __restrict__ inA, int CA,
    const float* __restrict__ inB, int CB,
    const float* __restrict__ wgt, const float* __restrict__ bias,
    float* __restrict__ out, int H, int W, int nChunk, int Ctot)
{
    constexpr int KK  = K * K;
    constexpr int PAD = K / 2;
    constexpr int TH  = 8 * RPT;
    constexpr int SW  = (K == 3) ? 18 : 22;
    constexpr int SH  = TH + K - 1;
    __shared__ float s_in[SH * SW];
    __shared__ __align__(16) float s_w[KK * COC];

    const int tx = threadIdx.x & 15;
    const int ty = threadIdx.x >> 4;          // 0..7
    const int x0 = blockIdx.x * 16;
    const int y0 = blockIdx.y * TH;
    const int z  = blockIdx.z;
    const int b     = z / nChunk;
    const int chunk = z - b * nChunk;
    const int co0   = chunk * COC;
    const int Cin = CA + CB;
    const size_t HW = (size_t)H * W;

    float acc[COC * RPT];
#pragma unroll
    for (int i = 0; i < COC * RPT; i++) acc[i] = 0.f;

    for (int cin = 0; cin < Cin; cin++) {
        const float* src = (cin < CA)
            ? inA + ((size_t)b * CA + cin) * HW
            : inB + ((size_t)b * CB + (cin - CA)) * HW;

        __syncthreads();   // protect previous iteration's smem reads
        for (int i = threadIdx.x; i < SH * SW; i += 128) {
            int iy = i / SW, ix = i - iy * SW;
            int gy = y0 + iy - PAD, gx = x0 + ix - PAD;
            float v = 0.f;
            if ((unsigned)gy < (unsigned)H && (unsigned)gx < (unsigned)W)
                v = src[(size_t)gy * W + gx];
            s_in[i] = v;
        }
        for (int i = threadIdx.x; i < KK * COC; i += 128) {
            int k = i / COC, co = i - k * COC;
            s_w[i] = wgt[((size_t)(co0 + co) * Cin + cin) * KK + k];
        }
        __syncthreads();

#pragma unroll
        for (int k = 0; k < KK; k++) {
            const int ky = k / K, kx = k - ky * K;
            float v[RPT];
#pragma unroll
            for (int r = 0; r < RPT; r++)
                v[r] = s_in[(ty + 8 * r + ky) * SW + tx + kx];

            if (COC % 4 == 0) {
#pragma unroll
                for (int c4 = 0; c4 < COC / 4; c4++) {
                    float4 w = *reinterpret_cast<const float4*>(
                        &s_w[k * COC + 4 * c4]);
#pragma unroll
                    for (int r = 0; r < RPT; r++) {
                        acc[(4 * c4 + 0) * RPT + r] += v[r] * w.x;
                        acc[(4 * c4 + 1) * RPT + r] += v[r] * w.y;
                        acc[(4 * c4 + 2) * RPT + r] += v[r] * w.z;
                        acc[(4 * c4 + 3) * RPT + r] += v[r] * w.w;
                    }
                }
            } else {
#pragma unroll
                for (int co = 0; co < COC; co++) {
                    float w = s_w[k * COC + co];
#pragma unroll
                    for (int r = 0; r < RPT; r++)
                        acc[co * RPT + r] += v[r] * w;
                }
            }
        }
    }

    const int x = x0 + tx;
#pragma unroll
    for (int co = 0; co < COC; co++) {
        float bb = bias[co0 + co];
        size_t cbase = ((size_t)b * Ctot + co0 + co) * HW;
#pragma unroll
        for (int r = 0; r < RPT; r++) {
            float s = acc[co * RPT + r] + bb;
            if (ACT == ACT_RELU)      s = fmaxf(s, 0.f);
            else if (ACT == ACT_TANH) s = tanhf(s);
            else if (ACT == ACT_SIG)  s = 1.f / (1.f + expf(-s));
            out[cbase + (size_t)(y0 + ty + 8 * r) * W + x] = s;
        }
    }
}

// ---------------------------------------------------------------------------
// 2x2 maxpool (stride 2)
// ---------------------------------------------------------------------------
__global__ void maxpool_kernel(const float* __restrict__ in,
                               float* __restrict__ out,
                               int n, int Ho, int Wo)
{
    int idx = blockIdx.x * 256 + threadIdx.x;
    if (idx >= n) return;
    int x = idx % Wo;
    int t = idx / Wo;
    int y = t % Ho;
    int bc = t / Ho;
    int Wi = Wo * 2;
    const float* p = in + ((size_t)bc * (Ho * 2) + 2 * y) * Wi + 2 * x;
    float a = fmaxf(p[0], p[1]);
    float c = fmaxf(p[Wi], p[Wi + 1]);
    out[idx] = fmaxf(a, c);
}

// ---------------------------------------------------------------------------
// 2x bilinear upsample, half-pixel centers, edge clamp
// ---------------------------------------------------------------------------
__global__ void upsample_kernel(const float* __restrict__ in,
                                float* __restrict__ out,
                                int n, int Hi, int Wi)
{
    int idx = blockIdx.x * 256 + threadIdx.x;
    if (idx >= n) return;
    int Wo = Wi * 2, Ho = Hi * 2;
    int x = idx % Wo;
    int t = idx / Wo;
    int y = t % Ho;
    int bc = t / Ho;
    int xi = x >> 1, yi = y >> 1;
    int xa, xb; float wxa;
    if (x & 1) { xa = xi; xb = min(xi + 1, Wi - 1); wxa = 0.75f; }
    else       { xa = max(xi - 1, 0); xb = xi;      wxa = 0.25f; }
    int ya, yb; float wya;
    if (y & 1) { ya = yi; yb = min(yi + 1, Hi - 1); wya = 0.75f; }
    else       { ya = max(yi - 1, 0); yb = yi;      wya = 0.25f; }
    const float* p = in + (size_t)bc * Hi * Wi;
    float r0 = wxa * p[ya * Wi + xa] + (1.f - wxa) * p[ya * Wi + xb];
    float r1 = wxa * p[yb * Wi + xa] + (1.f - wxa) * p[yb * Wi + xb];
    out[idx] = wya * r0 + (1.f - wya) * r1;
}

// ---------------------------------------------------------------------------
// LRNN.  h_k = (1-p_k)*x_k + p_k*h_{k-1}.  Flipped directions keep outputs
// in SCAN order, so one ascending pass computes all 4 directions of one
// orientation writing at index k (backward scans read index L-1-k).
// Horizontal: P channels {c, 32+c};  Vertical: {16+c, 48+c}.
// ---------------------------------------------------------------------------
__global__ void lrnn_h_kernel(const float* __restrict__ xin,
                              const float* __restrict__ fm,
                              float* __restrict__ out)
{
    int r = blockIdx.x * 256 + threadIdx.x;      // over 8*16*256 rows
    if (r >= 8 * 16 * 256) return;
    int y = r & 255;
    int c = (r >> 8) & 15;
    int b = r >> 12;
    const float* X  = xin + (((size_t)b * 16 + c) << 16) + (size_t)y * 256;
    const float* P0 = fm  + (((size_t)b * 64 + c)      << 16) + (size_t)y * 256;
    const float* P2 = fm  + (((size_t)b * 64 + 32 + c) << 16) + (size_t)y * 256;
    float* O        = out + (((size_t)b * 16 + c) << 16) + (size_t)y * 256;
    float h0 = 0.f, h1 = 0.f, h2 = 0.f, h3 = 0.f;
    for (int k = 0; k < 256; k++) {
        int j = 255 - k;
        float xf = X[k], xb = X[j];
        float p0 = P0[k], p1 = P2[k], p2 = P0[j], p3 = P2[j];
        h0 = xf + p0 * (h0 - xf);
        h1 = xf + p1 * (h1 - xf);
        h2 = xb + p2 * (h2 - xb);
        h3 = xb + p3 * (h3 - xb);
        O[k] = fmaxf(fmaxf(h0, h1), fmaxf(h2, h3));
    }
}

__global__ void lrnn_v_kernel(const float* __restrict__ xin,
                              const float* __restrict__ fm,
                              float* __restrict__ out)
{
    int r = blockIdx.x * 256 + threadIdx.x;      // over 8*16*256 columns
    if (r >= 8 * 16 * 256) return;
    int x = r & 255;
    int c = (r >> 8) & 15;
    int b = r >> 12;
    const float* X  = xin + (((size_t)b * 16 + c) << 16) + x;
    const float* P1 = fm  + (((size_t)b * 64 + 16 + c) << 16) + x;
    const float* P3 = fm  + (((size_t)b * 64 + 48 + c) << 16) + x;
    float* O        = out + (((size_t)b * 16 + c) << 16) + x;
    float h0 = 0.f, h1 = 0.f, h2 = 0.f, h3 = 0.f;
    for (int k = 0; k < 256; k++) {
        int ko = k << 8;
        int jo = (255 - k) << 8;
        float xf = X[ko], xb = X[jo];
        float p0 = P1[ko], p1 = P3[ko], p2 = P1[jo], p3 = P3[jo];
        h0 = xf + p0 * (h0 - xf);
        h1 = xf + p1 * (h1 - xf);
        h2 = xb + p2 * (h2 - xb);
        h3 = xb + p3 * (h3 - xb);
        float m = fmaxf(fmaxf(h0, h1), fmaxf(h2, h3));
        O[ko] = fmaxf(O[ko], m);
    }
}

// ---------------------------------------------------------------------------
// launch
// ---------------------------------------------------------------------------
extern "C" void kernel_launch(void* const* d_in, const int* in_sizes, int n_in,
                              void* d_out, int out_size)
{
    const float* img = (const float*)d_in[0];
    const float* w1 = (const float*)d_in[1],  *b1 = (const float*)d_in[2];
    const float* w2 = (const float*)d_in[3],  *b2 = (const float*)d_in[4];
    const float* w3 = (const float*)d_in[5],  *b3 = (const float*)d_in[6];
    const float* w4 = (const float*)d_in[7],  *b4 = (const float*)d_in[8];
    const float* w5 = (const float*)d_in[9],  *b5 = (const float*)d_in[10];
    const float* w6 = (const float*)d_in[11], *b6 = (const float*)d_in[12];
    const float* w7 = (const float*)d_in[13], *b7 = (const float*)d_in[14];
    const float* w8 = (const float*)d_in[15], *b8 = (const float*)d_in[16];
    const float* w9 = (const float*)d_in[17], *b9 = (const float*)d_in[18];
    const float* wi = (const float*)d_in[19], *bi = (const float*)d_in[20];
    const float* wo = (const float*)d_in[21], *bo = (const float*)d_in[22];
    float* outp = (float*)d_out;

    float* buf = nullptr;
    cudaGetSymbolAddress((void**)&buf, g_buf);
    float* X1 = buf + O_X1;  float* P1 = buf + O_P1;
    float* X2 = buf + O_X2;  float* P2 = buf + O_P2;
    float* X3 = buf + O_X3;  float* P3 = buf + O_P3;
    float* X4 = buf + O_X4;  float* P4 = buf + O_P4;
    float* X5 = buf + O_X5;  float* U5 = buf + O_U5;
    float* X6 = buf + O_X6;  float* U6 = buf + O_U6;
    float* X7 = buf + O_X7;  float* U7 = buf + O_U7;
    float* X8 = buf + O_X8;  float* U8 = buf + O_U8;
    float* FM = buf + O_FM;  float* XIN = buf + O_XIN;
    float* RMAX = buf + O_RMAX;

    // grid helper: tile 16 x (8*RPT); chunk folded into z.
    auto cgrid = [](int W, int H, int RPT, int nChunk) {
        return dim3(W / 16, H / (8 * RPT), 8 * nChunk);
    };
    auto eg = [](size_t n) { return dim3((unsigned)((n + 255) / 256)); };

    // encoder
    conv_kernel<5,16,ACT_RELU,4><<<cgrid(256,256,4,1),128>>>(img,15, nullptr,0, w1,b1, X1, 256,256, 1,16);
    maxpool_kernel<<<eg(N_P1),256>>>(X1, P1, (int)N_P1, 128,128);
    conv_kernel<3,16,ACT_RELU,4><<<cgrid(128,128,4,2),128>>>(P1,16, nullptr,0, w2,b2, X2, 128,128, 2,32);
    maxpool_kernel<<<eg(N_P2),256>>>(X2, P2, (int)N_P2, 64,64);
    conv_kernel<3,16,ACT_RELU,4><<<cgrid(64,64,4,2),128>>>(P2,32, nullptr,0, w3,b3, X3, 64,64, 2,32);
    maxpool_kernel<<<eg(N_P3),256>>>(X3, P3, (int)N_P3, 32,32);
    conv_kernel<3,16,ACT_RELU,1><<<cgrid(32,32,1,2),128>>>(P3,32, nullptr,0, w4,b4, X4, 32,32, 2,32);
    maxpool_kernel<<<eg(N_P4),256>>>(X4, P4, (int)N_P4, 16,16);
    conv_kernel<3,16,ACT_RELU,1><<<cgrid(16,16,1,4),128>>>(P4,32, nullptr,0, w5,b5, X5, 16,16, 4,64);

    // decoder
    upsample_kernel<<<eg(N_U5),256>>>(X5, U5, (int)N_U5, 16,16);
    conv_kernel<3,16,ACT_RELU,1><<<cgrid(32,32,1,2),128>>>(U5,64, X4,32, w6,b6, X6, 32,32, 2,32);
    upsample_kernel<<<eg(N_U6),256>>>(X6, U6, (int)N_U6, 32,32);
    conv_kernel<3,16,ACT_RELU,4><<<cgrid(64,64,4,2),128>>>(U6,32, X3,32, w7,b7, X7, 64,64, 2,32);
    upsample_kernel<<<eg(N_U7),256>>>(X7, U7, (int)N_U7, 64,64);
    conv_kernel<3,16,ACT_RELU,4><<<cgrid(128,128,4,2),128>>>(U7,32, X2,32, w8,b8, X8, 128,128, 2,32);
    upsample_kernel<<<eg(N_U8),256>>>(X8, U8, (int)N_U8, 128,128);
    conv_kernel<3,16,ACT_TANH,4><<<cgrid(256,256,4,4),128>>>(U8,32, X1,16, w9,b9, FM, 256,256, 4,64);

    // input projection
    conv_kernel<3,16,ACT_NONE,4><<<cgrid(256,256,4,1),128>>>(img,15, nullptr,0, wi,bi, XIN, 256,256, 1,16);

    // spatial RNN: horizontal pass writes RMAX, vertical pass max-combines
    lrnn_h_kernel<<<128,256>>>(XIN, FM, RMAX);
    lrnn_v_kernel<<<128,256>>>(XIN, FM, RMAX);

    // output conv + sigmoid
    conv_kernel<3,3,ACT_SIG,4><<<cgrid(256,256,4,1),128>>>(RMAX,16, nullptr,0, wo,bo, outp, 256,256, 1,3);
}